// round 7
// baseline (speedup 1.0000x reference)
#include <cuda_runtime.h>

#define NN 50000
#define EE 1600000
#define FULL 0xffffffffu
#define CSRB 96

typedef unsigned long long u64t;

__device__ __forceinline__ u64t pk(float lo, float hi) {
    u64t r; asm("mov.b64 %0,{%1,%2};" : "=l"(r) : "f"(lo), "f"(hi)); return r;
}
__device__ __forceinline__ void upk(u64t v, float& lo, float& hi) {
    asm("mov.b64 {%0,%1},%2;" : "=f"(lo), "=f"(hi) : "l"(v));
}
__device__ __forceinline__ u64t f2fma(u64t a, u64t b, u64t c) {
    u64t d; asm("fma.rn.f32x2 %0,%1,%2,%3;" : "=l"(d) : "l"(a), "l"(b), "l"(c)); return d;
}
// streaming (evict-first) loads for the ef stream
__device__ __forceinline__ ulonglong2 ldcs2(const ulonglong2* p) {
    ulonglong2 r;
    asm("ld.global.cs.v2.u64 {%0,%1},[%2];" : "=l"(r.x), "=l"(r.y) : "l"(p));
    return r;
}
// L2 evict_last policy + cache_hint loads for the hot k/v tables
__device__ __forceinline__ u64t mkpol() {
    u64t p; asm("createpolicy.fractional.L2::evict_last.b64 %0, 1.0;" : "=l"(p)); return p;
}
__device__ __forceinline__ ulonglong2 ldlast2(const ulonglong2* p, u64t pol) {
    ulonglong2 r;
    asm("ld.global.L2::cache_hint.v2.u64 {%0,%1},[%2],%3;"
        : "=l"(r.x), "=l"(r.y) : "l"(p), "l"(pol));
    return r;
}
__device__ __forceinline__ u64t ldlast1(const u64t* p, u64t pol) {
    u64t r;
    asm("ld.global.L2::cache_hint.u64 %0,[%1],%2;" : "=l"(r) : "l"(p), "l"(pol));
    return r;
}

// ---------------- scratch (device globals; no allocation allowed) ----------
__device__ float g_q1[NN*128];
__device__ float g_k1[NN*128];
__device__ float g_v1[NN*128];
__device__ float g_h [NN*128];
__device__ float g_t1[NN*256];
__device__ float g_q2[NN*64];
__device__ float g_k2[NN*64];
__device__ float g_v2[NN*64];
__device__ float g_s2[NN*64];
__device__ float g_t2[NN*64];
__device__ int   g_cnt[NN];
__device__ int   g_rowptr[NN+1];
__device__ int   g_woff[NN];
__device__ int   g_bsum[64];
__device__ int2  g_edges[EE];
__device__ int   g_gen;       // zero-init; monotonically increases across calls
__device__ int   g_arrived;   // zero-init; returns to 0 after each barrier

// ---------------- fused CSR kernel with device-wide barrier -----------------
__device__ __forceinline__ void gbar() {
    __syncthreads();
    if (threadIdx.x == 0) {
        int gen = ((volatile int*)&g_gen)[0];
        __threadfence();
        int prev = atomicAdd(&g_arrived, 1);
        if (prev == CSRB-1) {
            g_arrived = 0;
            __threadfence();
            atomicAdd(&g_gen, 1);
        } else {
            while (((volatile int*)&g_gen)[0] == gen) {}
        }
        __threadfence();
    }
    __syncthreads();
}

__global__ void __launch_bounds__(1024) k_csr(const int* __restrict__ src,
                                              const int* __restrict__ dst) {
    __shared__ int s[1024];
    int tid = blockIdx.x*1024 + threadIdx.x;
    const int nth = CSRB*1024;

    // zero counts
    for (int i = tid; i < NN; i += nth) g_cnt[i] = 0;
    gbar();
    // histogram
    for (int e = tid; e < EE; e += nth) atomicAdd(&g_cnt[dst[e]], 1);
    gbar();
    // local exclusive scans (blocks 0..48, 1024 elems each)
    if (blockIdx.x < 49) {
        int i = blockIdx.x*1024 + threadIdx.x;
        int v = (i < NN) ? g_cnt[i] : 0;
        s[threadIdx.x] = v;
        __syncthreads();
        for (int off = 1; off < 1024; off <<= 1) {
            int t = (threadIdx.x >= off) ? s[threadIdx.x - off] : 0;
            __syncthreads();
            s[threadIdx.x] += t;
            __syncthreads();
        }
        if (i < NN) g_rowptr[i] = s[threadIdx.x] - v;
        if (threadIdx.x == 1023) g_bsum[blockIdx.x] = s[1023];
    }
    gbar();
    // scan of 49 block sums (block 0)
    if (blockIdx.x == 0) {
        int t = threadIdx.x;
        int v = (t < 49) ? g_bsum[t] : 0;
        if (t < 64) s[t] = v;
        __syncthreads();
        for (int off = 1; off < 64; off <<= 1) {
            int x = (t >= off && t < 64) ? s[t-off] : 0;
            __syncthreads();
            if (t < 64) s[t] += x;
            __syncthreads();
        }
        if (t < 49) g_bsum[t] = s[t] - v;
        if (t == 48) g_rowptr[NN] = s[48];
    }
    gbar();
    // add block offsets
    for (int i = tid; i < NN; i += nth) {
        int r = g_rowptr[i] + g_bsum[i >> 10];
        g_rowptr[i] = r;
        g_woff[i] = r;
    }
    gbar();
    // scatter
    for (int e = tid; e < EE; e += nth) {
        int d = dst[e];
        int p = atomicAdd(&g_woff[d], 1);
        g_edges[p] = make_int2(src[e], e);
    }
}

// ---------------- node linear layers: BN=32, LDS.128 pairs ------------------
__global__ void __launch_bounds__(128) k_node1(const float* __restrict__ x,
    const float* __restrict__ Wq, const float* __restrict__ bq,
    const float* __restrict__ Wk, const float* __restrict__ bk,
    const float* __restrict__ Wv, const float* __restrict__ bv,
    const float* __restrict__ Ws, const float* __restrict__ bs)
{
    const int CIN = 128, COUT = 128, BN = 32;
    int mat = blockIdx.y;
    const float* W = (mat==0)?Wq:((mat==1)?Wk:((mat==2)?Wv:Ws));
    const float* b = (mat==0)?bq:((mat==1)?bk:((mat==2)?bv:bs));
    float* o = (mat==0)?g_q1:((mat==1)?g_k1:((mat==2)?g_v1:g_h));
    int n0 = blockIdx.x * BN;

    __shared__ float xs[CIN][BN+4];   // pad 4 -> 16B-aligned rows, 4-way STS
    for (int i = threadIdx.x; i < BN*CIN; i += COUT) {
        int nn = i >> 7, c = i & 127;
        xs[c][nn] = (n0+nn < NN) ? x[(size_t)(n0+nn)*CIN + c] : 0.f;
    }
    __syncthreads();

    int col = threadIdx.x;
    float bb = b[col];
    u64t accP[16];
    u64t bbP = pk(bb, bb);
    #pragma unroll
    for (int j = 0; j < 16; j++) accP[j] = bbP;

    #pragma unroll 2
    for (int k = 0; k < CIN; k++) {
        float wv = W[(size_t)k*COUT + col];
        u64t wvP = pk(wv, wv);
        const ulonglong2* xr = (const ulonglong2*)&xs[k][0];
        #pragma unroll
        for (int j = 0; j < 8; j++) {
            ulonglong2 xp = xr[j];
            accP[2*j]   = f2fma(wvP, xp.x, accP[2*j]);
            accP[2*j+1] = f2fma(wvP, xp.y, accP[2*j+1]);
        }
    }
    #pragma unroll
    for (int j = 0; j < 16; j++) {
        float a0, a1; upk(accP[j], a0, a1);
        int r0 = n0 + 2*j, r1 = n0 + 2*j + 1;
        if (r0 < NN) o[(size_t)r0*COUT + col] = a0;
        if (r1 < NN) o[(size_t)r1*COUT + col] = a1;
    }
}

__global__ void __launch_bounds__(64) k_node2(
    const float* __restrict__ Wq, const float* __restrict__ bq,
    const float* __restrict__ Wk, const float* __restrict__ bk,
    const float* __restrict__ Wv, const float* __restrict__ bv,
    const float* __restrict__ Ws, const float* __restrict__ bs)
{
    const int CIN = 128, COUT = 64, BN = 32;
    int mat = blockIdx.y;
    const float* W = (mat==0)?Wq:((mat==1)?Wk:((mat==2)?Wv:Ws));
    const float* b = (mat==0)?bq:((mat==1)?bk:((mat==2)?bv:bs));
    float* o = (mat==0)?g_q2:((mat==1)?g_k2:((mat==2)?g_v2:g_s2));
    int n0 = blockIdx.x * BN;

    __shared__ float xs[CIN][BN+4];
    for (int i = threadIdx.x; i < BN*CIN; i += COUT) {
        int nn = i >> 7, c = i & 127;
        xs[c][nn] = (n0+nn < NN) ? g_h[(size_t)(n0+nn)*CIN + c] : 0.f;
    }
    __syncthreads();

    int col = threadIdx.x;
    float bb = b[col];
    u64t accP[16];
    u64t bbP = pk(bb, bb);
    #pragma unroll
    for (int j = 0; j < 16; j++) accP[j] = bbP;

    #pragma unroll 2
    for (int k = 0; k < CIN; k++) {
        float wv = W[(size_t)k*COUT + col];
        u64t wvP = pk(wv, wv);
        const ulonglong2* xr = (const ulonglong2*)&xs[k][0];
        #pragma unroll
        for (int j = 0; j < 8; j++) {
            ulonglong2 xp = xr[j];
            accP[2*j]   = f2fma(wvP, xp.x, accP[2*j]);
            accP[2*j+1] = f2fma(wvP, xp.y, accP[2*j+1]);
        }
    }
    #pragma unroll
    for (int j = 0; j < 16; j++) {
        float a0, a1; upk(accP[j], a0, a1);
        int r0 = n0 + 2*j, r1 = n0 + 2*j + 1;
        if (r0 < NN) o[(size_t)r0*COUT + col] = a0;
        if (r1 < NN) o[(size_t)r1*COUT + col] = a1;
    }
}

// ---------------- t tables --------------------------------------------------
__global__ void k_t1(const float* __restrict__ We1) {
    int h = blockIdx.y;
    __shared__ float Wt[32][65];
    __shared__ float qsm[32][33];
    int tid = threadIdx.x;
    for (int i = tid; i < 64*32; i += 256) {
        int d = i >> 5, c = i & 31;
        Wt[c][d] = We1[(size_t)d*128 + h*32 + c];
    }
    int n0 = blockIdx.x * 32;
    for (int i = tid; i < 32*32; i += 256) {
        int nn = i >> 5, c = i & 31;
        qsm[nn][c] = (n0+nn < NN) ? g_q1[(size_t)(n0+nn)*128 + h*32 + c] : 0.f;
    }
    __syncthreads();
    int d = tid & 63, nb = tid >> 6;
    #pragma unroll
    for (int p = 0; p < 8; p++) {
        int nn = p*4 + nb;
        float acc = 0.f;
        #pragma unroll
        for (int c = 0; c < 32; c++) acc += qsm[nn][c] * Wt[c][d];
        if (n0+nn < NN) g_t1[(size_t)(n0+nn)*256 + h*64 + d] = acc;
    }
}

__global__ void k_t2(const float* __restrict__ We2) {
    __shared__ float Wt[64][65];
    __shared__ float qsm[32][65];
    int tid = threadIdx.x;
    for (int i = tid; i < 64*64; i += 256) {
        int d = i >> 6, c = i & 63;
        Wt[c][d] = We2[(size_t)d*64 + c];
    }
    int n0 = blockIdx.x * 32;
    for (int i = tid; i < 32*64; i += 256) {
        int nn = i >> 6, c = i & 63;
        qsm[nn][c] = (n0+nn < NN) ? g_q2[(size_t)(n0+nn)*64 + c] : 0.f;
    }
    __syncthreads();
    int d = tid & 63, nb = tid >> 6;
    #pragma unroll
    for (int p = 0; p < 8; p++) {
        int nn = p*4 + nb;
        float acc = 0.f;
        #pragma unroll
        for (int c = 0; c < 64; c++) acc += qsm[nn][c] * Wt[c][d];
        if (n0+nn < NN) g_t2[(size_t)(n0+nn)*64 + d] = acc;
    }
}

// ---------------- attention layer 1 (H=4, C=32) -----------------------------
// phase1: scores + g-accum (ef read ONCE, .cs); phase2: v-accum (evict_last)
__global__ void __launch_bounds__(256) k_attn1(const float* __restrict__ ef,
                                               const float* __restrict__ We1) {
    int lane = threadIdx.x & 31;
    int wl   = threadIdx.x >> 5;
    int n    = blockIdx.x*8 + wl;
    __shared__ float smemAll[8*512];
    float* qs  = smemAll + wl*512;   // 128 (pre-scaled)
    float* ts  = qs + 128;           // 256 (pre-scaled; reused as g in epilogue)
    float* aux = qs + 384;           // 128: w[32 edges][4 heads]
    if (n >= NN) return;

    const float inv_s = 0.1767766952966369f;   // 1/sqrt(32)
    {
        float4 q = ((const float4*)(g_q1 + (size_t)n*128))[lane];
        q.x*=inv_s; q.y*=inv_s; q.z*=inv_s; q.w*=inv_s;
        ((float4*)qs)[lane] = q;
        const float4* tsrc = (const float4*)(g_t1 + (size_t)n*256);
        float4 t0 = tsrc[lane], t1 = tsrc[lane+32];
        t0.x*=inv_s; t0.y*=inv_s; t0.z*=inv_s; t0.w*=inv_s;
        t1.x*=inv_s; t1.y*=inv_s; t1.z*=inv_s; t1.w*=inv_s;
        ((float4*)ts)[lane]    = t0;
        ((float4*)ts)[lane+32] = t1;
    }
    __syncwarp();

    u64t pol = mkpol();
    u64t agP[4][4];                 // per head: g chunks {l8*4..+3, 32+l8*4..+3}
    u64t accv0 = 0ull, accv1 = 0ull; // v channels lane*4..+3 (full sums)
    float den = 0.f;                 // head grp (full sum)
    #pragma unroll
    for (int h = 0; h < 4; h++) {
        agP[h][0]=0ull; agP[h][1]=0ull; agP[h][2]=0ull; agP[h][3]=0ull;
    }

    int rs = g_rowptr[n], re = g_rowptr[n+1];
    int l8 = lane & 7, grp = lane >> 3;
    const u64t* qU = (const u64t*)qs;
    const u64t* tU = (const u64t*)ts;
    int qo = l8*2;

    for (int base = rs; base < re; base += 32) {
        int cnt = min(32, re - base);
        int2 se = make_int2(0, 0);
        if (lane < cnt) se = g_edges[base + lane];
        // ---- phase 1: scores + g accumulation (8 lanes per edge) ----------
        #pragma unroll 2
        for (int sub = 0; sub < 8; sub++) {
            int el = sub*4 + grp;
            int esrc = __shfl_sync(FULL, se.x, el);
            int eeid = __shfl_sync(FULL, se.y, el);
            bool valid = el < cnt;
            const ulonglong2* kp = (const ulonglong2*)(g_k1 + (size_t)esrc*128);
            const ulonglong2* ep = (const ulonglong2*)(ef   + (size_t)eeid*64);
            ulonglong2 kv0 = ldlast2(kp+l8, pol),    kv1 = ldlast2(kp+8+l8, pol);
            ulonglong2 kv2 = ldlast2(kp+16+l8, pol), kv3 = ldlast2(kp+24+l8, pol);
            ulonglong2 ev0 = ldcs2(ep + l8), ev1 = ldcs2(ep + 8 + l8);

            u64t aP0 = f2fma(kv0.x, qU[qo],    f2fma(kv0.y, qU[qo+1],    0ull));
            u64t aP1 = f2fma(kv1.x, qU[16+qo], f2fma(kv1.y, qU[16+qo+1], 0ull));
            u64t aP2 = f2fma(kv2.x, qU[32+qo], f2fma(kv2.y, qU[32+qo+1], 0ull));
            u64t aP3 = f2fma(kv3.x, qU[48+qo], f2fma(kv3.y, qU[48+qo+1], 0ull));

            aP0 = f2fma(ev0.x, tU[qo],       aP0); aP0 = f2fma(ev0.y, tU[qo+1],       aP0);
            aP0 = f2fma(ev1.x, tU[16+qo],    aP0); aP0 = f2fma(ev1.y, tU[16+qo+1],    aP0);
            aP1 = f2fma(ev0.x, tU[32+qo],    aP1); aP1 = f2fma(ev0.y, tU[32+qo+1],    aP1);
            aP1 = f2fma(ev1.x, tU[48+qo],    aP1); aP1 = f2fma(ev1.y, tU[48+qo+1],    aP1);
            aP2 = f2fma(ev0.x, tU[64+qo],    aP2); aP2 = f2fma(ev0.y, tU[64+qo+1],    aP2);
            aP2 = f2fma(ev1.x, tU[80+qo],    aP2); aP2 = f2fma(ev1.y, tU[80+qo+1],    aP2);
            aP3 = f2fma(ev0.x, tU[96+qo],    aP3); aP3 = f2fma(ev0.y, tU[96+qo+1],    aP3);
            aP3 = f2fma(ev1.x, tU[112+qo],   aP3); aP3 = f2fma(ev1.y, tU[112+qo+1],   aP3);

            float a0, a1, a2, a3, t;
            upk(aP0, a0, t); a0 += t;
            upk(aP1, a1, t); a1 += t;
            upk(aP2, a2, t); a2 += t;
            upk(aP3, a3, t); a3 += t;
            #pragma unroll
            for (int o = 1; o <= 4; o <<= 1) {
                a0 += __shfl_xor_sync(FULL, a0, o);
                a1 += __shfl_xor_sync(FULL, a1, o);
                a2 += __shfl_xor_sync(FULL, a2, o);
                a3 += __shfl_xor_sync(FULL, a3, o);
            }
            float w0 = valid ? __expf(a0) : 0.f;
            float w1 = valid ? __expf(a1) : 0.f;
            float w2 = valid ? __expf(a2) : 0.f;
            float w3 = valid ? __expf(a3) : 0.f;
            u64t wP0 = pk(w0,w0), wP1 = pk(w1,w1), wP2 = pk(w2,w2), wP3 = pk(w3,w3);

            agP[0][0] = f2fma(wP0, ev0.x, agP[0][0]); agP[0][1] = f2fma(wP0, ev0.y, agP[0][1]);
            agP[0][2] = f2fma(wP0, ev1.x, agP[0][2]); agP[0][3] = f2fma(wP0, ev1.y, agP[0][3]);
            agP[1][0] = f2fma(wP1, ev0.x, agP[1][0]); agP[1][1] = f2fma(wP1, ev0.y, agP[1][1]);
            agP[1][2] = f2fma(wP1, ev1.x, agP[1][2]); agP[1][3] = f2fma(wP1, ev1.y, agP[1][3]);
            agP[2][0] = f2fma(wP2, ev0.x, agP[2][0]); agP[2][1] = f2fma(wP2, ev0.y, agP[2][1]);
            agP[2][2] = f2fma(wP2, ev1.x, agP[2][2]); agP[2][3] = f2fma(wP2, ev1.y, agP[2][3]);
            agP[3][0] = f2fma(wP3, ev0.x, agP[3][0]); agP[3][1] = f2fma(wP3, ev0.y, agP[3][1]);
            agP[3][2] = f2fma(wP3, ev1.x, agP[3][2]); agP[3][3] = f2fma(wP3, ev1.y, agP[3][3]);

            if (l8 == 0) *(float4*)(aux + el*4) = make_float4(w0, w1, w2, w3);
        }
        __syncwarp();
        // ---- phase 2: v accumulation (whole-warp coalesced, evict_last) ---
        #pragma unroll 4
        for (int e = 0; e < cnt; e++) {
            int esrc = __shfl_sync(FULL, se.x, e);
            float w = aux[e*4 + grp];
            den += w;
            u64t wP = pk(w, w);
            ulonglong2 vv = ldlast2((const ulonglong2*)(g_v1 + (size_t)esrc*128) + lane, pol);
            accv0 = f2fma(wP, vv.x, accv0);
            accv1 = f2fma(wP, vv.y, accv1);
        }
        __syncwarp();
    }

    // ---- epilogue: reduce g over groups, then We1 GEMM ----------------------
    float4 aglo[4], aghi[4];
    #pragma unroll
    for (int h = 0; h < 4; h++) {
        upk(agP[h][0], aglo[h].x, aglo[h].y); upk(agP[h][1], aglo[h].z, aglo[h].w);
        upk(agP[h][2], aghi[h].x, aghi[h].y); upk(agP[h][3], aghi[h].z, aghi[h].w);
    }
    #pragma unroll
    for (int o = 8; o <= 16; o <<= 1) {
        #pragma unroll
        for (int h = 0; h < 4; h++) {
            aglo[h].x += __shfl_xor_sync(FULL, aglo[h].x, o);
            aglo[h].y += __shfl_xor_sync(FULL, aglo[h].y, o);
            aglo[h].z += __shfl_xor_sync(FULL, aglo[h].z, o);
            aglo[h].w += __shfl_xor_sync(FULL, aglo[h].w, o);
            aghi[h].x += __shfl_xor_sync(FULL, aghi[h].x, o);
            aghi[h].y += __shfl_xor_sync(FULL, aghi[h].y, o);
            aghi[h].z += __shfl_xor_sync(FULL, aghi[h].z, o);
            aghi[h].w += __shfl_xor_sync(FULL, aghi[h].w, o);
        }
    }
    __syncwarp();
    float* gs = ts;   // reuse
    {
        float4 glo = (grp==0)?aglo[0]:((grp==1)?aglo[1]:((grp==2)?aglo[2]:aglo[3]));
        float4 ghi = (grp==0)?aghi[0]:((grp==1)?aghi[1]:((grp==2)?aghi[2]:aghi[3]));
        *(float4*)(gs + grp*64 + l8*4)      = glo;
        *(float4*)(gs + grp*64 + 32 + l8*4) = ghi;
    }
    __syncwarp();

    float4 og = make_float4(0.f,0.f,0.f,0.f);
    const float* Wc = We1 + grp*32 + l8*4;
    const float* gh = gs + grp*64;
    #pragma unroll 8
    for (int d = 0; d < 64; d++) {
        float g = gh[d];
        float4 wr = *(const float4*)(Wc + (size_t)d*128);
        og.x += g*wr.x; og.y += g*wr.y; og.z += g*wr.z; og.w += g*wr.w;
    }
    float inv = (den > 0.f) ? (1.f/den) : 0.f;
    float4 av; upk(accv0, av.x, av.y); upk(accv1, av.z, av.w);
    float4 skip = *(const float4*)(g_h + (size_t)n*128 + lane*4);
    float4 o;
    o.x = fmaxf(fmaf(av.x + og.x, inv, skip.x), 0.f);
    o.y = fmaxf(fmaf(av.y + og.y, inv, skip.y), 0.f);
    o.z = fmaxf(fmaf(av.z + og.z, inv, skip.z), 0.f);
    o.w = fmaxf(fmaf(av.w + og.w, inv, skip.w), 0.f);
    *(float4*)(g_h + (size_t)n*128 + lane*4) = o;
}

// ---------------- attention layer 2 (H=1, C=64) ------------------------------
__global__ void __launch_bounds__(256) k_attn2(const float* __restrict__ ef,
                                               const float* __restrict__ We2,
                                               float* __restrict__ out) {
    int lane = threadIdx.x & 31;
    int wl   = threadIdx.x >> 5;
    int n    = blockIdx.x*8 + wl;
    __shared__ float smemAll[8*160];
    float* qs  = smemAll + wl*160;  // 64 (pre-scaled)
    float* ts  = qs + 64;           // 64 (pre-scaled; reused as g)
    float* aux = qs + 128;          // 32: w per edge
    if (n >= NN) return;

    {
        float2 q = ((const float2*)(g_q2 + (size_t)n*64))[lane];
        q.x *= 0.125f; q.y *= 0.125f;
        ((float2*)qs)[lane] = q;
        float2 t = ((const float2*)(g_t2 + (size_t)n*64))[lane];
        t.x *= 0.125f; t.y *= 0.125f;
        ((float2*)ts)[lane] = t;
    }
    __syncwarp();

    u64t pol = mkpol();
    u64t agA0=0ull, agA1=0ull, agB0=0ull, agB1=0ull;  // g chunks {l8*4..,32+l8*4..}
    u64t accv = 0ull;                                  // v channels lane*2..+1
    float den = 0.f;
    int rs = g_rowptr[n], re = g_rowptr[n+1];
    int l8 = lane & 7, grp = lane >> 3;
    const u64t* qU = (const u64t*)qs;
    const u64t* tU = (const u64t*)ts;
    int qo = l8*2;

    for (int base = rs; base < re; base += 32) {
        int cnt = min(32, re - base);
        int2 se = make_int2(0, 0);
        if (lane < cnt) se = g_edges[base + lane];
        // phase 1: scores + g accumulation
        #pragma unroll 2
        for (int sub = 0; sub < 8; sub++) {
            int el = sub*4 + grp;
            int esrc = __shfl_sync(FULL, se.x, el);
            int eeid = __shfl_sync(FULL, se.y, el);
            bool valid = el < cnt;
            const ulonglong2* kp = (const ulonglong2*)(g_k2 + (size_t)esrc*64);
            const ulonglong2* ep = (const ulonglong2*)(ef   + (size_t)eeid*64);
            ulonglong2 kv0 = ldlast2(kp+l8, pol), kv1 = ldlast2(kp+8+l8, pol);
            ulonglong2 ev0 = ldcs2(ep + l8), ev1 = ldcs2(ep + 8 + l8);

            u64t aP = f2fma(kv0.x, qU[qo],    f2fma(kv0.y, qU[qo+1], 0ull));
            aP = f2fma(kv1.x, qU[16+qo], aP); aP = f2fma(kv1.y, qU[16+qo+1], aP);
            aP = f2fma(ev0.x, tU[qo],    aP); aP = f2fma(ev0.y, tU[qo+1],    aP);
            aP = f2fma(ev1.x, tU[16+qo], aP); aP = f2fma(ev1.y, tU[16+qo+1], aP);
            float a, t2v; upk(aP, a, t2v); a += t2v;
            a += __shfl_xor_sync(FULL, a, 1);
            a += __shfl_xor_sync(FULL, a, 2);
            a += __shfl_xor_sync(FULL, a, 4);
            float w = valid ? __expf(a) : 0.f;
            u64t wP = pk(w, w);
            agA0 = f2fma(wP, ev0.x, agA0); agA1 = f2fma(wP, ev0.y, agA1);
            agB0 = f2fma(wP, ev1.x, agB0); agB1 = f2fma(wP, ev1.y, agB1);
            if (l8 == 0) aux[el] = w;
        }
        __syncwarp();
        // phase 2: v accumulation
        #pragma unroll 4
        for (int e = 0; e < cnt; e++) {
            int esrc = __shfl_sync(FULL, se.x, e);
            float w = aux[e];
            den += w;
            u64t wP = pk(w, w);
            u64t vv = ldlast1((const u64t*)(g_v2 + (size_t)esrc*64) + lane, pol);
            accv = f2fma(wP, vv, accv);
        }
        __syncwarp();
    }

    // epilogue: reduce g over groups
    float4 ga, gb;
    upk(agA0, ga.x, ga.y); upk(agA1, ga.z, ga.w);
    upk(agB0, gb.x, gb.y); upk(agB1, gb.z, gb.w);
    #pragma unroll
    for (int o = 8; o <= 16; o <<= 1) {
        ga.x += __shfl_xor_sync(FULL, ga.x, o); ga.y += __shfl_xor_sync(FULL, ga.y, o);
        ga.z += __shfl_xor_sync(FULL, ga.z, o); ga.w += __shfl_xor_sync(FULL, ga.w, o);
        gb.x += __shfl_xor_sync(FULL, gb.x, o); gb.y += __shfl_xor_sync(FULL, gb.y, o);
        gb.z += __shfl_xor_sync(FULL, gb.z, o); gb.w += __shfl_xor_sync(FULL, gb.w, o);
    }
    __syncwarp();
    if (grp == 0) {
        *(float4*)(ts + l8*4)      = ga;
        *(float4*)(ts + 32 + l8*4) = gb;
    }
    __syncwarp();

    float2 og = make_float2(0.f,0.f);
    const float* Wc = We2 + lane*2;
    #pragma unroll 8
    for (int d = 0; d < 64; d++) {
        float g = ts[d];
        float2 wr = *(const float2*)(Wc + (size_t)d*64);
        og.x += g*wr.x; og.y += g*wr.y;
    }
    float inv = (den > 0.f) ? (1.f/den) : 0.f;
    float2 av; upk(accv, av.x, av.y);
    float2 s2 = *(const float2*)(g_s2 + (size_t)n*64 + lane*2);
    float2 o;
    o.x = fmaf(av.x + og.x, inv, s2.x);
    o.y = fmaf(av.y + og.y, inv, s2.y);
    *(float2*)(out + (size_t)n*64 + lane*2) = o;
}

// ---------------- launch -----------------------------------------------------
extern "C" void kernel_launch(void* const* d_in, const int* in_sizes, int n_in,
                              void* d_out, int out_size)
{
    const float* x   = (const float*)d_in[0];
    const float* ef  = (const float*)d_in[1];
    const int*   ei  = (const int*)  d_in[2];
    const float *Wq1 = (const float*)d_in[3],  *bq1 = (const float*)d_in[4];
    const float *Wk1 = (const float*)d_in[5],  *bk1 = (const float*)d_in[6];
    const float *Wv1 = (const float*)d_in[7],  *bv1 = (const float*)d_in[8];
    const float *We1 = (const float*)d_in[9];
    const float *Ws1 = (const float*)d_in[10], *bs1 = (const float*)d_in[11];
    const float *Wq2 = (const float*)d_in[12], *bq2 = (const float*)d_in[13];
    const float *Wk2 = (const float*)d_in[14], *bk2 = (const float*)d_in[15];
    const float *Wv2 = (const float*)d_in[16], *bv2 = (const float*)d_in[17];
    const float *We2 = (const float*)d_in[18];
    const float *Ws2 = (const float*)d_in[19], *bs2 = (const float*)d_in[20];
    float* out = (float*)d_out;

    const int* srcp = ei;        // edge_index[0]
    const int* dstp = ei + EE;   // edge_index[1]

    k_csr<<<CSRB, 1024>>>(srcp, dstp);                          // 1
    dim3 g1((NN+31)/32, 4);
    k_node1<<<g1, 128>>>(x, Wq1,bq1, Wk1,bk1, Wv1,bv1, Ws1,bs1); // 2
    dim3 gt1((NN+31)/32, 4);
    k_t1   <<<gt1, 256>>>(We1);                                  // 3
    k_attn1<<<(NN+7)/8, 256>>>(ef, We1);                         // 4  <- profiled
    k_node2<<<g1, 64>>>(Wq2,bq2, Wk2,bk2, Wv2,bv2, Ws2,bs2);     // 5
    k_t2   <<<(NN+31)/32, 256>>>(We2);                           // 6
    k_attn2<<<(NN+7)/8, 256>>>(ef, We2, out);                    // 7
}

// round 8
// speedup vs baseline: 1.1336x; 1.1336x over previous
#include <cuda_runtime.h>

#define NN 50000
#define EE 1600000
#define FULL 0xffffffffu
#define CSRB 96

typedef unsigned long long u64t;

__device__ __forceinline__ u64t pk(float lo, float hi) {
    u64t r; asm("mov.b64 %0,{%1,%2};" : "=l"(r) : "f"(lo), "f"(hi)); return r;
}
__device__ __forceinline__ void upk(u64t v, float& lo, float& hi) {
    asm("mov.b64 {%0,%1},%2;" : "=f"(lo), "=f"(hi) : "l"(v));
}
__device__ __forceinline__ u64t f2fma(u64t a, u64t b, u64t c) {
    u64t d; asm("fma.rn.f32x2 %0,%1,%2,%3;" : "=l"(d) : "l"(a), "l"(b), "l"(c)); return d;
}
// streaming (evict-first) loads for the ef stream (no reuse)
__device__ __forceinline__ ulonglong2 ldcs2(const ulonglong2* p) {
    ulonglong2 r;
    asm("ld.global.cs.v2.u64 {%0,%1},[%2];" : "=l"(r.x), "=l"(r.y) : "l"(p));
    return r;
}
__device__ __forceinline__ u64t ldcs1(const u64t* p) {
    u64t r; asm("ld.global.cs.u64 %0,[%1];" : "=l"(r) : "l"(p)); return r;
}

// ---------------- scratch (device globals; no allocation allowed) ----------
__device__ float g_q1[NN*128];
__device__ float g_k1[NN*128];
__device__ float g_v1[NN*128];
__device__ float g_h [NN*128];
__device__ float g_t1[NN*256];
__device__ float g_q2[NN*64];
__device__ float g_k2[NN*64];
__device__ float g_v2[NN*64];
__device__ float g_s2[NN*64];
__device__ float g_t2[NN*64];
__device__ float g_w [EE*4];     // per-edge attention weights (layer1: 4 heads)
__device__ int   g_cnt[NN];
__device__ int   g_rowptr[NN+1];
__device__ int   g_woff[NN];
__device__ int   g_bsum[64];
__device__ int2  g_edges[EE];    // CSR by dst: {src, eid}
__device__ int   g_edst[EE];     // dst per CSR slot
__device__ int   g_gen;
__device__ int   g_arrived;

// ---------------- fused CSR kernel with device-wide barrier -----------------
__device__ __forceinline__ void gbar() {
    __syncthreads();
    if (threadIdx.x == 0) {
        int gen = ((volatile int*)&g_gen)[0];
        __threadfence();
        int prev = atomicAdd(&g_arrived, 1);
        if (prev == CSRB-1) {
            g_arrived = 0;
            __threadfence();
            atomicAdd(&g_gen, 1);
        } else {
            while (((volatile int*)&g_gen)[0] == gen) {}
        }
        __threadfence();
    }
    __syncthreads();
}

__global__ void __launch_bounds__(1024) k_csr(const int* __restrict__ src,
                                              const int* __restrict__ dst) {
    __shared__ int s[1024];
    int tid = blockIdx.x*1024 + threadIdx.x;
    const int nth = CSRB*1024;

    for (int i = tid; i < NN; i += nth) g_cnt[i] = 0;
    gbar();
    for (int e = tid; e < EE; e += nth) atomicAdd(&g_cnt[dst[e]], 1);
    gbar();
    if (blockIdx.x < 49) {
        int i = blockIdx.x*1024 + threadIdx.x;
        int v = (i < NN) ? g_cnt[i] : 0;
        s[threadIdx.x] = v;
        __syncthreads();
        for (int off = 1; off < 1024; off <<= 1) {
            int t = (threadIdx.x >= off) ? s[threadIdx.x - off] : 0;
            __syncthreads();
            s[threadIdx.x] += t;
            __syncthreads();
        }
        if (i < NN) g_rowptr[i] = s[threadIdx.x] - v;
        if (threadIdx.x == 1023) g_bsum[blockIdx.x] = s[1023];
    }
    gbar();
    if (blockIdx.x == 0) {
        int t = threadIdx.x;
        int v = (t < 49) ? g_bsum[t] : 0;
        if (t < 64) s[t] = v;
        __syncthreads();
        for (int off = 1; off < 64; off <<= 1) {
            int x = (t >= off && t < 64) ? s[t-off] : 0;
            __syncthreads();
            if (t < 64) s[t] += x;
            __syncthreads();
        }
        if (t < 49) g_bsum[t] = s[t] - v;
        if (t == 48) g_rowptr[NN] = s[48];
    }
    gbar();
    for (int i = tid; i < NN; i += nth) {
        int r = g_rowptr[i] + g_bsum[i >> 10];
        g_rowptr[i] = r;
        g_woff[i] = r;
    }
    gbar();
    for (int e = tid; e < EE; e += nth) {
        int d = dst[e];
        int p = atomicAdd(&g_woff[d], 1);
        g_edges[p] = make_int2(src[e], e);
        g_edst[p] = d;
    }
}

// ---------------- node linear layers (R4/R6 measured-good) ------------------
__global__ void k_node1(const float* __restrict__ x,
    const float* __restrict__ Wq, const float* __restrict__ bq,
    const float* __restrict__ Wk, const float* __restrict__ bk,
    const float* __restrict__ Wv, const float* __restrict__ bv,
    const float* __restrict__ Ws, const float* __restrict__ bs)
{
    const int CIN = 128, COUT = 128, BN = 16;
    int mat = blockIdx.y;
    const float* W = (mat==0)?Wq:((mat==1)?Wk:((mat==2)?Wv:Ws));
    const float* b = (mat==0)?bq:((mat==1)?bk:((mat==2)?bv:bs));
    float* o = (mat==0)?g_q1:((mat==1)?g_k1:((mat==2)?g_v1:g_h));
    int n0 = blockIdx.x * BN;

    __shared__ float xs[CIN][BN];
    for (int i = threadIdx.x; i < BN*CIN; i += COUT) {
        int nn = i / CIN, c = i % CIN;
        xs[c][nn] = x[(size_t)(n0+nn)*CIN + c];
    }
    __syncthreads();

    int col = threadIdx.x;
    float bb = b[col];
    u64t accP[8];
    u64t bbP = pk(bb, bb);
    #pragma unroll
    for (int j = 0; j < 8; j++) accP[j] = bbP;

    #pragma unroll 2
    for (int k = 0; k < CIN; k++) {
        float wv = W[(size_t)k*COUT + col];
        u64t wvP = pk(wv, wv);
        const u64t* xr = (const u64t*)xs[k];
        #pragma unroll
        for (int j = 0; j < 8; j++) accP[j] = f2fma(wvP, xr[j], accP[j]);
    }
    #pragma unroll
    for (int j = 0; j < 8; j++) {
        float a0, a1; upk(accP[j], a0, a1);
        o[(size_t)(n0+2*j)*COUT + col]   = a0;
        o[(size_t)(n0+2*j+1)*COUT + col] = a1;
    }
}

__global__ void k_node2(
    const float* __restrict__ Wq, const float* __restrict__ bq,
    const float* __restrict__ Wk, const float* __restrict__ bk,
    const float* __restrict__ Wv, const float* __restrict__ bv,
    const float* __restrict__ Ws, const float* __restrict__ bs)
{
    const int CIN = 128, COUT = 64, BN = 16;
    int mat = blockIdx.y;
    const float* W = (mat==0)?Wq:((mat==1)?Wk:((mat==2)?Wv:Ws));
    const float* b = (mat==0)?bq:((mat==1)?bk:((mat==2)?bv:bs));
    float* o = (mat==0)?g_q2:((mat==1)?g_k2:((mat==2)?g_v2:g_s2));
    int n0 = blockIdx.x * BN;

    __shared__ float xs[CIN][BN];
    for (int i = threadIdx.x; i < BN*CIN; i += COUT) {
        int nn = i / CIN, c = i % CIN;
        xs[c][nn] = g_h[(size_t)(n0+nn)*CIN + c];
    }
    __syncthreads();

    int col = threadIdx.x;
    float bb = b[col];
    u64t accP[8];
    u64t bbP = pk(bb, bb);
    #pragma unroll
    for (int j = 0; j < 8; j++) accP[j] = bbP;

    #pragma unroll 2
    for (int k = 0; k < CIN; k++) {
        float wv = W[(size_t)k*COUT + col];
        u64t wvP = pk(wv, wv);
        const u64t* xr = (const u64t*)xs[k];
        #pragma unroll
        for (int j = 0; j < 8; j++) accP[j] = f2fma(wvP, xr[j], accP[j]);
    }
    #pragma unroll
    for (int j = 0; j < 8; j++) {
        float a0, a1; upk(accP[j], a0, a1);
        o[(size_t)(n0+2*j)*COUT + col]   = a0;
        o[(size_t)(n0+2*j+1)*COUT + col] = a1;
    }
}

// ---------------- t tables --------------------------------------------------
__global__ void k_t1(const float* __restrict__ We1) {
    int h = blockIdx.y;
    __shared__ float Wt[32][65];
    __shared__ float qsm[32][33];
    int tid = threadIdx.x;
    for (int i = tid; i < 64*32; i += 256) {
        int d = i >> 5, c = i & 31;
        Wt[c][d] = We1[(size_t)d*128 + h*32 + c];
    }
    int n0 = blockIdx.x * 32;
    for (int i = tid; i < 32*32; i += 256) {
        int nn = i >> 5, c = i & 31;
        qsm[nn][c] = (n0+nn < NN) ? g_q1[(size_t)(n0+nn)*128 + h*32 + c] : 0.f;
    }
    __syncthreads();
    int d = tid & 63, nb = tid >> 6;
    #pragma unroll
    for (int p = 0; p < 8; p++) {
        int nn = p*4 + nb;
        float acc = 0.f;
        #pragma unroll
        for (int c = 0; c < 32; c++) acc += qsm[nn][c] * Wt[c][d];
        if (n0+nn < NN) g_t1[(size_t)(n0+nn)*256 + h*64 + d] = acc;
    }
}

__global__ void k_t2(const float* __restrict__ We2) {
    __shared__ float Wt[64][65];
    __shared__ float qsm[32][65];
    int tid = threadIdx.x;
    for (int i = tid; i < 64*64; i += 256) {
        int d = i >> 6, c = i & 63;
        Wt[c][d] = We2[(size_t)d*64 + c];
    }
    int n0 = blockIdx.x * 32;
    for (int i = tid; i < 32*64; i += 256) {
        int nn = i >> 6, c = i & 63;
        qsm[nn][c] = (n0+nn < NN) ? g_q2[(size_t)(n0+nn)*64 + c] : 0.f;
    }
    __syncthreads();
    int d = tid & 63, nb = tid >> 6;
    #pragma unroll
    for (int p = 0; p < 8; p++) {
        int nn = p*4 + nb;
        float acc = 0.f;
        #pragma unroll
        for (int c = 0; c < 64; c++) acc += qsm[nn][c] * Wt[c][d];
        if (n0+nn < NN) g_t2[(size_t)(n0+nn)*64 + d] = acc;
    }
}

// ---------------- layer-1 scores: edge-parallel, 8 lanes per edge -----------
__global__ void __launch_bounds__(256) k_score1(const float* __restrict__ ef) {
    int tid  = threadIdx.x;
    int lane = tid & 31;
    int l8   = lane & 7;
    int i    = blockIdx.x*32 + (tid >> 3);   // CSR slot; EE % 32 == 0
    if (i >= EE) return;

    int2 se = g_edges[i];
    int  dn = g_edst[i];
    const ulonglong2* kp = (const ulonglong2*)(g_k1 + (size_t)se.x*128);
    const ulonglong2* qp = (const ulonglong2*)(g_q1 + (size_t)dn*128);
    const ulonglong2* ep = (const ulonglong2*)(ef   + (size_t)se.y*64);
    const ulonglong2* tp = (const ulonglong2*)(g_t1 + (size_t)dn*256);

    u64t a[4];
    #pragma unroll
    for (int h = 0; h < 4; h++) {
        ulonglong2 kv = kp[h*8 + l8];
        ulonglong2 qv = qp[h*8 + l8];
        a[h] = f2fma(kv.x, qv.x, 0ull);
        a[h] = f2fma(kv.y, qv.y, a[h]);
    }
    ulonglong2 ev0 = ldcs2(ep + l8), ev1 = ldcs2(ep + 8 + l8);
    #pragma unroll
    for (int h = 0; h < 4; h++) {
        ulonglong2 tv0 = tp[h*16 + l8], tv1 = tp[h*16 + 8 + l8];
        a[h] = f2fma(ev0.x, tv0.x, a[h]); a[h] = f2fma(ev0.y, tv0.y, a[h]);
        a[h] = f2fma(ev1.x, tv1.x, a[h]); a[h] = f2fma(ev1.y, tv1.y, a[h]);
    }
    float s0,s1,s2,s3,t;
    upk(a[0],s0,t); s0+=t;
    upk(a[1],s1,t); s1+=t;
    upk(a[2],s2,t); s2+=t;
    upk(a[3],s3,t); s3+=t;
    #pragma unroll
    for (int o = 1; o <= 4; o <<= 1) {
        s0 += __shfl_xor_sync(FULL, s0, o);
        s1 += __shfl_xor_sync(FULL, s1, o);
        s2 += __shfl_xor_sync(FULL, s2, o);
        s3 += __shfl_xor_sync(FULL, s3, o);
    }
    if (l8 == 0) {
        const float inv_s = 0.1767766952966369f;   // 1/sqrt(32)
        float4 w4;
        w4.x = __expf(s0*inv_s); w4.y = __expf(s1*inv_s);
        w4.z = __expf(s2*inv_s); w4.w = __expf(s3*inv_s);
        *(float4*)(g_w + (size_t)i*4) = w4;
    }
}

// ---------------- layer-1 aggregate: node-per-warp, no reductions -----------
__global__ void __launch_bounds__(256) k_agg1(const float* __restrict__ ef,
                                              const float* __restrict__ We1) {
    int lane = threadIdx.x & 31;
    int wl   = threadIdx.x >> 5;
    int n    = blockIdx.x*8 + wl;
    __shared__ float smemAll[8*384];
    float* aux = smemAll + wl*384;    // 128: w[32][4]
    float* gsm = aux + 128;           // 256: g[4][64]
    if (n >= NN) return;

    int l8 = lane & 7, grp = lane >> 3;
    u64t accv0 = 0ull, accv1 = 0ull;  // v channels lane*4..+3 (head grp)
    u64t ag[4] = {0ull,0ull,0ull,0ull}; // g[h] channels lane*2..+1
    float den = 0.f;

    int rs = g_rowptr[n], re = g_rowptr[n+1];
    for (int base = rs; base < re; base += 32) {
        int cnt = min(32, re - base);
        int2 se = make_int2(0, 0);
        if (lane < cnt) {
            se = g_edges[base + lane];
            *(float4*)(aux + lane*4) = *(const float4*)(g_w + (size_t)(base+lane)*4);
        }
        __syncwarp();
        #pragma unroll 2
        for (int e = 0; e < cnt; e++) {
            int esrc = __shfl_sync(FULL, se.x, e);
            int eeid = __shfl_sync(FULL, se.y, e);
            const float* we = aux + e*4;
            float w0 = we[0], w1 = we[1], w2 = we[2], w3 = we[3];
            float wg = (grp==0)?w0:((grp==1)?w1:((grp==2)?w2:w3));
            den += wg;
            u64t wgP = pk(wg, wg);
            ulonglong2 vv = ((const ulonglong2*)(g_v1 + (size_t)esrc*128))[lane];
            accv0 = f2fma(wgP, vv.x, accv0);
            accv1 = f2fma(wgP, vv.y, accv1);
            u64t ev = ldcs1((const u64t*)(ef + (size_t)eeid*64) + lane);
            ag[0] = f2fma(pk(w0,w0), ev, ag[0]);
            ag[1] = f2fma(pk(w1,w1), ev, ag[1]);
            ag[2] = f2fma(pk(w2,w2), ev, ag[2]);
            ag[3] = f2fma(pk(w3,w3), ev, ag[3]);
        }
        __syncwarp();
    }

    // write g to smem: gsm[h*64 + lane*2 .. +1]
    u64t* gU = (u64t*)gsm;
    gU[0*32 + lane] = ag[0];
    gU[1*32 + lane] = ag[1];
    gU[2*32 + lane] = ag[2];
    gU[3*32 + lane] = ag[3];
    __syncwarp();

    float4 og = make_float4(0.f,0.f,0.f,0.f);
    const float* Wc = We1 + grp*32 + l8*4;
    const float* gh = gsm + grp*64;
    #pragma unroll 8
    for (int d = 0; d < 64; d++) {
        float g = gh[d];
        float4 wr = *(const float4*)(Wc + (size_t)d*128);
        og.x += g*wr.x; og.y += g*wr.y; og.z += g*wr.z; og.w += g*wr.w;
    }
    float inv = (den > 0.f) ? (1.f/den) : 0.f;
    float4 av; upk(accv0, av.x, av.y); upk(accv1, av.z, av.w);
    float4 skip = *(const float4*)(g_h + (size_t)n*128 + lane*4);
    float4 o;
    o.x = fmaxf(fmaf(av.x + og.x, inv, skip.x), 0.f);
    o.y = fmaxf(fmaf(av.y + og.y, inv, skip.y), 0.f);
    o.z = fmaxf(fmaf(av.z + og.z, inv, skip.z), 0.f);
    o.w = fmaxf(fmaf(av.w + og.w, inv, skip.w), 0.f);
    *(float4*)(g_h + (size_t)n*128 + lane*4) = o;
}

// ---------------- layer-2 scores: edge-parallel ------------------------------
__global__ void __launch_bounds__(256) k_score2(const float* __restrict__ ef) {
    int tid  = threadIdx.x;
    int lane = tid & 31;
    int l8   = lane & 7;
    int i    = blockIdx.x*32 + (tid >> 3);
    if (i >= EE) return;

    int2 se = g_edges[i];
    int  dn = g_edst[i];
    const ulonglong2* kp = (const ulonglong2*)(g_k2 + (size_t)se.x*64);
    const ulonglong2* qp = (const ulonglong2*)(g_q2 + (size_t)dn*64);
    const ulonglong2* ep = (const ulonglong2*)(ef   + (size_t)se.y*64);
    const ulonglong2* tp = (const ulonglong2*)(g_t2 + (size_t)dn*64);

    ulonglong2 kv0 = kp[l8], kv1 = kp[8+l8];
    ulonglong2 qv0 = qp[l8], qv1 = qp[8+l8];
    ulonglong2 ev0 = ldcs2(ep + l8), ev1 = ldcs2(ep + 8 + l8);
    ulonglong2 tv0 = tp[l8], tv1 = tp[8+l8];

    u64t aP = f2fma(kv0.x, qv0.x, 0ull);
    aP = f2fma(kv0.y, qv0.y, aP);
    aP = f2fma(kv1.x, qv1.x, aP);
    aP = f2fma(kv1.y, qv1.y, aP);
    aP = f2fma(ev0.x, tv0.x, aP);
    aP = f2fma(ev0.y, tv0.y, aP);
    aP = f2fma(ev1.x, tv1.x, aP);
    aP = f2fma(ev1.y, tv1.y, aP);
    float s, t; upk(aP, s, t); s += t;
    s += __shfl_xor_sync(FULL, s, 1);
    s += __shfl_xor_sync(FULL, s, 2);
    s += __shfl_xor_sync(FULL, s, 4);
    if (l8 == 0) g_w[i] = __expf(s*0.125f);
}

// ---------------- layer-2 aggregate ------------------------------------------
__global__ void __launch_bounds__(256) k_agg2(const float* __restrict__ ef,
                                              const float* __restrict__ We2,
                                              float* __restrict__ out) {
    int lane = threadIdx.x & 31;
    int wl   = threadIdx.x >> 5;
    int n    = blockIdx.x*8 + wl;
    __shared__ float smemAll[8*96];
    float* aux = smemAll + wl*96;   // 32: w per edge
    float* gsm = aux + 32;          // 64: g
    if (n >= NN) return;

    u64t accv = 0ull;   // v channels lane*2..+1
    u64t ag   = 0ull;   // g channels lane*2..+1
    float den = 0.f;
    int rs = g_rowptr[n], re = g_rowptr[n+1];

    for (int base = rs; base < re; base += 32) {
        int cnt = min(32, re - base);
        int2 se = make_int2(0, 0);
        if (lane < cnt) {
            se = g_edges[base + lane];
            aux[lane] = g_w[base + lane];
        }
        __syncwarp();
        #pragma unroll 2
        for (int e = 0; e < cnt; e++) {
            int esrc = __shfl_sync(FULL, se.x, e);
            int eeid = __shfl_sync(FULL, se.y, e);
            float w = aux[e];
            den += w;
            u64t wP = pk(w, w);
            u64t vv = ((const u64t*)(g_v2 + (size_t)esrc*64))[lane];
            accv = f2fma(wP, vv, accv);
            u64t ev = ldcs1((const u64t*)(ef + (size_t)eeid*64) + lane);
            ag = f2fma(wP, ev, ag);
        }
        __syncwarp();
    }

    ((u64t*)gsm)[lane] = ag;
    __syncwarp();

    float2 og = make_float2(0.f,0.f);
    const float* Wc = We2 + lane*2;
    #pragma unroll 8
    for (int d = 0; d < 64; d++) {
        float g = gsm[d];
        float2 wr = *(const float2*)(Wc + (size_t)d*64);
        og.x += g*wr.x; og.y += g*wr.y;
    }
    float inv = (den > 0.f) ? (1.f/den) : 0.f;
    float2 av; upk(accv, av.x, av.y);
    float2 s2 = *(const float2*)(g_s2 + (size_t)n*64 + lane*2);
    float2 o;
    o.x = fmaf(av.x + og.x, inv, s2.x);
    o.y = fmaf(av.y + og.y, inv, s2.y);
    *(float2*)(out + (size_t)n*64 + lane*2) = o;
}

// ---------------- launch -----------------------------------------------------
extern "C" void kernel_launch(void* const* d_in, const int* in_sizes, int n_in,
                              void* d_out, int out_size)
{
    const float* x   = (const float*)d_in[0];
    const float* ef  = (const float*)d_in[1];
    const int*   ei  = (const int*)  d_in[2];
    const float *Wq1 = (const float*)d_in[3],  *bq1 = (const float*)d_in[4];
    const float *Wk1 = (const float*)d_in[5],  *bk1 = (const float*)d_in[6];
    const float *Wv1 = (const float*)d_in[7],  *bv1 = (const float*)d_in[8];
    const float *We1 = (const float*)d_in[9];
    const float *Ws1 = (const float*)d_in[10], *bs1 = (const float*)d_in[11];
    const float *Wq2 = (const float*)d_in[12], *bq2 = (const float*)d_in[13];
    const float *Wk2 = (const float*)d_in[14], *bk2 = (const float*)d_in[15];
    const float *Wv2 = (const float*)d_in[16], *bv2 = (const float*)d_in[17];
    const float *We2 = (const float*)d_in[18];
    const float *Ws2 = (const float*)d_in[19], *bs2 = (const float*)d_in[20];
    float* out = (float*)d_out;

    const int* srcp = ei;        // edge_index[0]
    const int* dstp = ei + EE;   // edge_index[1]

    k_csr<<<CSRB, 1024>>>(srcp, dstp);                             // 1
    dim3 g1(NN/16, 4);
    k_node1 <<<g1, 128>>>(x, Wq1,bq1, Wk1,bk1, Wv1,bv1, Ws1,bs1);  // 2
    dim3 gt1((NN+31)/32, 4);
    k_t1    <<<gt1, 256>>>(We1);                                   // 3
    k_score1<<<EE/32, 256>>>(ef);                                  // 4 <- profiled
    k_agg1  <<<(NN+7)/8, 256>>>(ef, We1);                          // 5
    k_node2 <<<g1, 64>>>(Wq2,bq2, Wk2,bk2, Wv2,bv2, Ws2,bs2);      // 6
    k_t2    <<<(NN+31)/32, 256>>>(We2);                            // 7
    k_score2<<<EE/32, 256>>>(ef);                                  // 8
    k_agg2  <<<(NN+7)/8, 256>>>(ef, We2, out);                     // 9
}